// round 13
// baseline (speedup 1.0000x reference)
#include <cuda_runtime.h>

// ---------------------------------------------------------------------------
// SINDy autoencoder forward (batch-1, HBM-bound, ~545MB weights/call).
// Output: [z(16) | dz(16) | dzb(16) | xb(16384) | dxb(16384)] = 32816 f32
// R13: exact R4 + two targeted L2 prefetches into idle-DRAM windows:
//      - enc1 block(0,0) prefetches the small matrices (for k_small)
//      - k_small prefetches all of wd_w1 (for dec1)
// ---------------------------------------------------------------------------

#define W0_OUT 4096
#define W0_IN  16384
#define W1_OUT 1024
#define LATENT 16
#define SINDY_DIM 984

__device__ float g_pre1[W0_OUT], g_u1[W0_OUT];
__device__ float g_pre2p[2 * W1_OUT], g_u2p[2 * W1_OUT];
__device__ float g_g1[1024],  g_p1[1024];
__device__ float g_q2[4096],  g_v2[4096];

__device__ __forceinline__ float sigf(float x) { return 1.0f / (1.0f + __expf(-x)); }
__device__ __forceinline__ float4 ldcs4(const float* p) { return __ldcs((const float4*)p); }

__device__ __forceinline__ void pdl_trigger() {
    asm volatile("griddepcontrol.launch_dependents;" ::: "memory");
}
__device__ __forceinline__ void pdl_wait() {
    asm volatile("griddepcontrol.wait;" ::: "memory");
}
__device__ __forceinline__ void l2_prefetch(const void* p) {
    asm volatile("prefetch.global.L2 [%0];" :: "l"(p));
}
template<int THREADS>
__device__ __forceinline__ void prefetch_tile(const float* base, size_t bytes) {
    const char* p = (const char*)base;
    for (size_t off = (size_t)threadIdx.x * 128; off < bytes; off += (size_t)THREADS * 128)
        l2_prefetch(p + off);
}

// ---------------------------------------------------------------------------
// Dual matvec over a K-chunk: outA[row]=W@a(+bias), outB[row]=W@b.
// ---------------------------------------------------------------------------
template<int KSTRIDE, int KCHUNK, int ROWS, int THREADS, bool SIG>
__device__ __forceinline__ void dual_body(
    const float* __restrict__ W,
    const float* __restrict__ av,
    const float* __restrict__ bv,
    const float* __restrict__ bias,
    float* __restrict__ outA,
    float* __restrict__ outB,
    int row0)
{
    constexpr int NW = THREADS / 32;
    constexpr int ITERS = KCHUNK / (THREADS * 4);
    const int tid = threadIdx.x;

    float accA[ROWS], accB[ROWS];
#pragma unroll
    for (int r = 0; r < ROWS; r++) { accA[r] = 0.0f; accB[r] = 0.0f; }

#pragma unroll 2
    for (int it = 0; it < ITERS; it++) {
        const int k = (it * THREADS + tid) * 4;
        float4 w4[ROWS];
#pragma unroll
        for (int r = 0; r < ROWS; r++)
            w4[r] = ldcs4(W + (size_t)r * KSTRIDE + k);
        float4 a4 = *(const float4*)(av + k);
        float4 b4 = *(const float4*)(bv + k);
        if (SIG) {
            float s;
            s = sigf(a4.x); b4.x *= s * (1.0f - s); a4.x = s;
            s = sigf(a4.y); b4.y *= s * (1.0f - s); a4.y = s;
            s = sigf(a4.z); b4.z *= s * (1.0f - s); a4.z = s;
            s = sigf(a4.w); b4.w *= s * (1.0f - s); a4.w = s;
        }
#pragma unroll
        for (int r = 0; r < ROWS; r++) {
            accA[r] = fmaf(w4[r].x, a4.x, accA[r]);
            accA[r] = fmaf(w4[r].y, a4.y, accA[r]);
            accA[r] = fmaf(w4[r].z, a4.z, accA[r]);
            accA[r] = fmaf(w4[r].w, a4.w, accA[r]);
            accB[r] = fmaf(w4[r].x, b4.x, accB[r]);
            accB[r] = fmaf(w4[r].y, b4.y, accB[r]);
            accB[r] = fmaf(w4[r].z, b4.z, accB[r]);
            accB[r] = fmaf(w4[r].w, b4.w, accB[r]);
        }
    }

    __shared__ float sA[NW][ROWS], sB[NW][ROWS];
    const int lane = tid & 31, warp = tid >> 5;
#pragma unroll
    for (int r = 0; r < ROWS; r++) {
        float vA = accA[r], vB = accB[r];
#pragma unroll
        for (int o = 16; o; o >>= 1) {
            vA += __shfl_xor_sync(0xffffffffu, vA, o);
            vB += __shfl_xor_sync(0xffffffffu, vB, o);
        }
        if (lane == 0) { sA[warp][r] = vA; sB[warp][r] = vB; }
    }
    __syncthreads();
    if (tid < ROWS) {
        float vA = 0.0f, vB = 0.0f;
#pragma unroll
        for (int w = 0; w < NW; w++) { vA += sA[w][tid]; vB += sB[w][tid]; }
        if (bias) vA += bias[row0 + tid];
        outA[row0 + tid] = vA;
        outB[row0 + tid] = vB;
    }
}

// enc L0 (256 MB, first in chain) — exact R4
__global__ void __launch_bounds__(256) k_enc0(
    const float* __restrict__ W, const float* __restrict__ x,
    const float* __restrict__ dx, const float* __restrict__ b)
{
    pdl_trigger();
    const int row0 = blockIdx.x * 4;
    dual_body<W0_IN, W0_IN, 4, 256, false>(
        W + (size_t)row0 * W0_IN, x, dx, b, g_pre1, g_u1, row0);
}

// enc L1, split-K x2 (16 MB) — R4 + small-matrix prefetch from block (0,0)
__global__ void __launch_bounds__(256) k_enc1(
    const float* __restrict__ W, const float* __restrict__ b,
    const float* __restrict__ we_w2, const float* __restrict__ E_w,
    const float* __restrict__ wd_w0)
{
    pdl_trigger();
    const int row0  = blockIdx.x * 4;
    const int split = blockIdx.y;
    const int koff  = split * 2048;
    const float* Wt = W + (size_t)row0 * W0_OUT + koff;
#pragma unroll
    for (int r = 0; r < 4; r++)
        prefetch_tile<256>(Wt + (size_t)r * W0_OUT, 8192);
    if (blockIdx.x == 0 && split == 0) {
        prefetch_tile<256>(we_w2, 16384 * 4);
        prefetch_tile<256>(E_w,   15744 * 4);
        prefetch_tile<256>(wd_w0, 16384 * 4);
    }
    pdl_wait();
    dual_body<W0_OUT, 2048, 4, 256, true>(
        Wt, g_pre1 + koff, g_u1 + koff,
        split == 0 ? b : nullptr,
        g_pre2p + split * W1_OUT, g_u2p + split * W1_OUT, row0);
}

// dec L1 (16 MB) — exact R4 (weights should be L2-hot from k_small's prefetch)
__global__ void __launch_bounds__(256) k_dec1(
    const float* __restrict__ W, const float* __restrict__ b)
{
    pdl_trigger();
    const int row0 = blockIdx.x * 4;
    const float* Wt = W + (size_t)row0 * 1024;
    prefetch_tile<256>(Wt, 4 * 1024 * 4);
    pdl_wait();
    dual_body<1024, 1024, 4, 256, false>(
        Wt, g_g1, g_p1, b, g_q2, g_v2, row0);
}

// dec L2 (256 MB, last) — exact R4
__global__ void __launch_bounds__(256) k_dec2(
    const float* __restrict__ W, const float* __restrict__ b,
    float* __restrict__ out)
{
    const int row0 = blockIdx.x * 4;
    const float* Wt = W + (size_t)row0 * 4096;
    prefetch_tile<256>(Wt, 4 * 4096 * 4);
    pdl_wait();
    dual_body<4096, 4096, 4, 256, true>(
        Wt, g_q2, g_v2, b, out + 48, out + 48 + 16384, row0);
}

// ---------------------------------------------------------------------------
// Middle chain, one block, 512 threads (R4) + wd_w1 prefetch for dec1.
// ---------------------------------------------------------------------------
#define SM_WE2   0
#define SM_EW    16384
#define SM_WD0   32128
#define SM_H2    48512
#define SM_T2    49536
#define SM_THETA 50560
#define SM_FLOATS 51544
#define SM_BYTES (SM_FLOATS * 4)

__global__ void __launch_bounds__(512) k_small(
    const float* __restrict__ we_w2, const float* __restrict__ we_b2,
    const float* __restrict__ E_w,   const float* __restrict__ E_b,
    const float* __restrict__ wd_w0, const float* __restrict__ wd_b0,
    const float* __restrict__ wd_w1,
    float* __restrict__ out)
{
    extern __shared__ float sm[];
    __shared__ float z[LATENT], dz[LATENT], dzb[LATENT];

    const int tid = threadIdx.x;
    const int lane = tid & 31, wid = tid >> 5;

    pdl_trigger();
    // own weights (likely L2-hot already from enc1 block(0,0))
    prefetch_tile<512>(we_w2, 16384 * 4);
    prefetch_tile<512>(E_w,   15744 * 4);
    prefetch_tile<512>(wd_w0, 16384 * 4);
    // dec1's entire weight matrix (16 MB) into the idle-DRAM window
    prefetch_tile<512>(wd_w1, (size_t)4096 * 1024 * 4);
    pdl_wait();

    for (int i = tid; i < 4096; i += 512)
        *(float4*)(sm + SM_WE2 + i * 4) = ldcs4(we_w2 + i * 4);
    for (int i = tid; i < 3936; i += 512)
        *(float4*)(sm + SM_EW + i * 4) = ldcs4(E_w + i * 4);
    for (int i = tid; i < 4096; i += 512)
        *(float4*)(sm + SM_WD0 + i * 4) = ldcs4(wd_w0 + i * 4);
    for (int i = tid; i < W1_OUT; i += 512) {
        float pre = g_pre2p[i] + g_pre2p[W1_OUT + i];
        float u   = g_u2p[i]   + g_u2p[W1_OUT + i];
        float s = sigf(pre);
        sm[SM_H2 + i] = s;
        sm[SM_T2 + i] = s * (1.0f - s) * u;
    }
    __syncthreads();

    {
        float az = 0.0f, ad = 0.0f;
        const float* wr = sm + SM_WE2 + wid * W1_OUT;
        for (int c = lane; c < W1_OUT; c += 32) {
            float w = wr[c];
            az = fmaf(w, sm[SM_H2 + c], az);
            ad = fmaf(w, sm[SM_T2 + c], ad);
        }
#pragma unroll
        for (int o = 16; o; o >>= 1) {
            az += __shfl_xor_sync(0xffffffffu, az, o);
            ad += __shfl_xor_sync(0xffffffffu, ad, o);
        }
        if (lane == 0) { z[wid] = az + we_b2[wid]; dz[wid] = ad; }
    }
    __syncthreads();

    if (tid < LATENT) { out[tid] = z[tid]; out[LATENT + tid] = dz[tid]; }

    for (int idx = tid; idx < SINDY_DIM; idx += 512) {
        float v;
        if (idx < 16) v = 1.0f;
        else if (idx < 32) v = z[idx - 16];
        else if (idx < 168) {
            int q = idx - 32, i = 0;
            for (;;) { int m = 16 - i; if (q < m) break; q -= m; i++; }
            v = z[i] * z[i + q];
        } else {
            int t = idx - 168, i = 0;
            for (;;) { int m = 16 - i; int c = m * (m + 1) / 2; if (t < c) break; t -= c; i++; }
            int j = i;
            for (;;) { int m = 16 - j; if (t < m) break; t -= m; j++; }
            v = z[i] * z[j] * z[j + t];
        }
        sm[SM_THETA + idx] = v;
    }
    __syncthreads();

    {
        float a = 0.0f;
        const float* er = sm + SM_EW + wid * SINDY_DIM;
        for (int c = lane; c < SINDY_DIM; c += 32)
            a = fmaf(er[c], sm[SM_THETA + c], a);
#pragma unroll
        for (int o = 16; o; o >>= 1)
            a += __shfl_xor_sync(0xffffffffu, a, o);
        if (lane == 0) dzb[wid] = a + E_b[wid];
    }
    __syncthreads();

    if (tid < LATENT) out[32 + tid] = dzb[tid];

    for (int row = tid; row < 1024; row += 512) {
        float a = wd_b0[row], bb = 0.0f;
        const float* wr = sm + SM_WD0 + row * LATENT;
#pragma unroll
        for (int c = 0; c < LATENT; c++) {
            float w = wr[c];
            a  = fmaf(w, z[c],   a);
            bb = fmaf(w, dzb[c], bb);
        }
        float s = sigf(a);
        g_g1[row] = s;
        g_p1[row] = s * (1.0f - s) * bb;
    }
}

// ---------------------------------------------------------------------------
extern "C" void kernel_launch(void* const* d_in, const int* in_sizes, int n_in,
                              void* d_out, int out_size)
{
    const float* x     = (const float*)d_in[0];
    const float* dx    = (const float*)d_in[1];
    const float* we_w0 = (const float*)d_in[3];
    const float* we_b0 = (const float*)d_in[4];
    const float* we_w1 = (const float*)d_in[5];
    const float* we_b1 = (const float*)d_in[6];
    const float* we_w2 = (const float*)d_in[7];
    const float* we_b2 = (const float*)d_in[8];
    const float* wd_w0 = (const float*)d_in[9];
    const float* wd_b0 = (const float*)d_in[10];
    const float* wd_w1 = (const float*)d_in[11];
    const float* wd_b1 = (const float*)d_in[12];
    const float* wd_w2 = (const float*)d_in[13];
    const float* wd_b2 = (const float*)d_in[14];
    const float* E_w   = (const float*)d_in[15];
    const float* E_b   = (const float*)d_in[16];
    float* out = (float*)d_out;

    cudaFuncSetAttribute(k_small, cudaFuncAttributeMaxDynamicSharedMemorySize, SM_BYTES);

    cudaLaunchAttribute attr[1];
    attr[0].id = cudaLaunchAttributeProgrammaticStreamSerialization;
    attr[0].val.programmaticStreamSerializationAllowed = 1;

    cudaLaunchConfig_t cfg{};
    cfg.blockDim = dim3(256, 1, 1);
    cfg.dynamicSmemBytes = 0;
    cfg.stream = 0;
    cfg.attrs = attr;
    cfg.numAttrs = 1;

    // 1) enc L0 (256 MB)
    cfg.gridDim = dim3(W0_OUT / 4, 1, 1);
    cudaLaunchKernelEx(&cfg, k_enc0, we_w0, x, dx, we_b0);

    // 2) enc L1 (16 MB, split-K x2) + small-matrix prefetch
    cfg.gridDim = dim3(W1_OUT / 4, 2, 1);
    cudaLaunchKernelEx(&cfg, k_enc1, we_w1, we_b1, we_w2, E_w, wd_w0);

    // 3) middle chain + wd_w1 prefetch
    {
        cudaLaunchConfig_t cs = cfg;
        cs.gridDim = dim3(1, 1, 1);
        cs.blockDim = dim3(512, 1, 1);
        cs.dynamicSmemBytes = SM_BYTES;
        cudaLaunchKernelEx(&cs, k_small, we_w2, we_b2, E_w, E_b,
                           wd_w0, wd_b0, wd_w1, out);
    }

    // 4) dec L1 (16 MB)
    cfg.gridDim = dim3(4096 / 4, 1, 1);
    cudaLaunchKernelEx(&cfg, k_dec1, wd_w1, wd_b1);

    // 5) dec L2 (256 MB)
    cfg.gridDim = dim3(16384 / 4, 1, 1);
    cudaLaunchKernelEx(&cfg, k_dec2, wd_w2, wd_b2, out);
}

// round 14
// speedup vs baseline: 1.2491x; 1.2491x over previous
#include <cuda_runtime.h>

// ---------------------------------------------------------------------------
// SINDy autoencoder forward (batch-1, HBM-bound, ~545MB weights/call).
// Output: [z(16) | dz(16) | dzb(16) | xb(16384) | dxb(16384)] = 32816 f32
// R14: R4 bodies; k_small head-fused into dec1 block 0 (flag-synchronized).
//      dec1 blocks prefetch their own weight tiles while block 0 runs the
//      small chain -> small-chain compute overlaps dec1's DRAM traffic.
// ---------------------------------------------------------------------------

#define W0_OUT 4096
#define W0_IN  16384
#define W1_OUT 1024
#define LATENT 16
#define SINDY_DIM 984

__device__ float g_pre1[W0_OUT], g_u1[W0_OUT];
__device__ float g_pre2p[2 * W1_OUT], g_u2p[2 * W1_OUT];
__device__ float g_g1[1024],  g_p1[1024];
__device__ float g_q2[4096],  g_v2[4096];
__device__ volatile unsigned g_flag;   // small chain done
__device__ unsigned g_fin;             // dec1 finish ticket (resets flag)

__device__ __forceinline__ float sigf(float x) { return 1.0f / (1.0f + __expf(-x)); }
__device__ __forceinline__ float4 ldcs4(const float* p) { return __ldcs((const float4*)p); }

__device__ __forceinline__ void pdl_trigger() {
    asm volatile("griddepcontrol.launch_dependents;" ::: "memory");
}
__device__ __forceinline__ void pdl_wait() {
    asm volatile("griddepcontrol.wait;" ::: "memory");
}
__device__ __forceinline__ void l2_prefetch(const void* p) {
    asm volatile("prefetch.global.L2 [%0];" :: "l"(p));
}
template<int THREADS>
__device__ __forceinline__ void prefetch_tile(const float* base, int bytes) {
    const char* p = (const char*)base;
    for (int off = threadIdx.x * 128; off < bytes; off += THREADS * 128)
        l2_prefetch(p + off);
}

// ---------------------------------------------------------------------------
// Dual matvec (R4-proven): outA[row]=W@a(+bias), outB[row]=W@b.
// ---------------------------------------------------------------------------
template<int KSTRIDE, int KCHUNK, int ROWS, int THREADS, bool SIG>
__device__ __forceinline__ void dual_body(
    const float* __restrict__ W,
    const float* __restrict__ av,
    const float* __restrict__ bv,
    const float* __restrict__ bias,
    float* __restrict__ outA,
    float* __restrict__ outB,
    int row0)
{
    constexpr int NW = THREADS / 32;
    constexpr int ITERS = KCHUNK / (THREADS * 4);
    const int tid = threadIdx.x;

    float accA[ROWS], accB[ROWS];
#pragma unroll
    for (int r = 0; r < ROWS; r++) { accA[r] = 0.0f; accB[r] = 0.0f; }

#pragma unroll 2
    for (int it = 0; it < ITERS; it++) {
        const int k = (it * THREADS + tid) * 4;
        float4 w4[ROWS];
#pragma unroll
        for (int r = 0; r < ROWS; r++)
            w4[r] = ldcs4(W + (size_t)r * KSTRIDE + k);
        float4 a4 = *(const float4*)(av + k);
        float4 b4 = *(const float4*)(bv + k);
        if (SIG) {
            float s;
            s = sigf(a4.x); b4.x *= s * (1.0f - s); a4.x = s;
            s = sigf(a4.y); b4.y *= s * (1.0f - s); a4.y = s;
            s = sigf(a4.z); b4.z *= s * (1.0f - s); a4.z = s;
            s = sigf(a4.w); b4.w *= s * (1.0f - s); a4.w = s;
        }
#pragma unroll
        for (int r = 0; r < ROWS; r++) {
            accA[r] = fmaf(w4[r].x, a4.x, accA[r]);
            accA[r] = fmaf(w4[r].y, a4.y, accA[r]);
            accA[r] = fmaf(w4[r].z, a4.z, accA[r]);
            accA[r] = fmaf(w4[r].w, a4.w, accA[r]);
            accB[r] = fmaf(w4[r].x, b4.x, accB[r]);
            accB[r] = fmaf(w4[r].y, b4.y, accB[r]);
            accB[r] = fmaf(w4[r].z, b4.z, accB[r]);
            accB[r] = fmaf(w4[r].w, b4.w, accB[r]);
        }
    }

    __shared__ float sA[NW][ROWS], sB[NW][ROWS];
    const int lane = tid & 31, warp = tid >> 5;
#pragma unroll
    for (int r = 0; r < ROWS; r++) {
        float vA = accA[r], vB = accB[r];
#pragma unroll
        for (int o = 16; o; o >>= 1) {
            vA += __shfl_xor_sync(0xffffffffu, vA, o);
            vB += __shfl_xor_sync(0xffffffffu, vB, o);
        }
        if (lane == 0) { sA[warp][r] = vA; sB[warp][r] = vB; }
    }
    __syncthreads();
    if (tid < ROWS) {
        float vA = 0.0f, vB = 0.0f;
#pragma unroll
        for (int w = 0; w < NW; w++) { vA += sA[w][tid]; vB += sB[w][tid]; }
        if (bias) vA += bias[row0 + tid];
        outA[row0 + tid] = vA;
        outB[row0 + tid] = vB;
    }
}

// enc L0 (256 MB, first in chain) — exact R4
__global__ void __launch_bounds__(256) k_enc0(
    const float* __restrict__ W, const float* __restrict__ x,
    const float* __restrict__ dx, const float* __restrict__ b)
{
    pdl_trigger();
    const int row0 = blockIdx.x * 4;
    dual_body<W0_IN, W0_IN, 4, 256, false>(
        W + (size_t)row0 * W0_IN, x, dx, b, g_pre1, g_u1, row0);
}

// enc L1, split-K x2 (16 MB) — R4 + small-matrix prefetch from block (0,0)
__global__ void __launch_bounds__(256) k_enc1(
    const float* __restrict__ W, const float* __restrict__ b,
    const float* __restrict__ we_w2, const float* __restrict__ E_w,
    const float* __restrict__ wd_w0)
{
    pdl_trigger();
    const int row0  = blockIdx.x * 4;
    const int split = blockIdx.y;
    const int koff  = split * 2048;
    const float* Wt = W + (size_t)row0 * W0_OUT + koff;
#pragma unroll
    for (int r = 0; r < 4; r++)
        prefetch_tile<256>(Wt + (size_t)r * W0_OUT, 8192);
    if (blockIdx.x == 0 && split == 0) {
        prefetch_tile<256>(we_w2, 16384 * 4);
        prefetch_tile<256>(E_w,   15744 * 4);
        prefetch_tile<256>(wd_w0, 16384 * 4);
    }
    pdl_wait();
    dual_body<W0_OUT, 2048, 4, 256, true>(
        Wt, g_pre1 + koff, g_u1 + koff,
        split == 0 ? b : nullptr,
        g_pre2p + split * W1_OUT, g_u2p + split * W1_OUT, row0);
}

// ---------------------------------------------------------------------------
// dec L1 (16 MB) + head-fused small chain in block 0.
// Blocks 1..1023: prefetch own tile -> pdl_wait -> spin on flag -> matvec.
// Block 0:        pdl_wait -> small chain -> flag=1 -> its own matvec.
// ---------------------------------------------------------------------------
__global__ void __launch_bounds__(256) k_dec1f(
    const float* __restrict__ W,     const float* __restrict__ b,
    const float* __restrict__ we_w2, const float* __restrict__ we_b2,
    const float* __restrict__ E_w,   const float* __restrict__ E_b,
    const float* __restrict__ wd_w0, const float* __restrict__ wd_b0,
    float* __restrict__ out)
{
    pdl_trigger();
    const int tid  = threadIdx.x;
    const int row0 = blockIdx.x * 4;
    const float* Wt = W + (size_t)row0 * 1024;
    prefetch_tile<256>(Wt, 4 * 1024 * 4);
    pdl_wait();

    if (blockIdx.x == 0) {
        // ================= small chain (256 threads) =================
        __shared__ float sh2[W1_OUT], st2[W1_OUT];
        __shared__ float theta[SINDY_DIM];
        __shared__ float z[LATENT], dz[LATENT], dzb[LATENT];
        const int lane = tid & 31, warp = tid >> 5;   // 8 warps

        for (int i = tid; i < W1_OUT; i += 256) {
            float pre = g_pre2p[i] + g_pre2p[W1_OUT + i];
            float u   = g_u2p[i]   + g_u2p[W1_OUT + i];
            float s = sigf(pre);
            sh2[i] = s;
            st2[i] = s * (1.0f - s) * u;
        }
        __syncthreads();

        // z, dz: 8 warps x 2 rows (we_w2 L2-hot)
        for (int r = warp; r < LATENT; r += 8) {
            float az = 0.0f, ad = 0.0f;
            const float* wr = we_w2 + (size_t)r * W1_OUT;
            for (int c = lane * 4; c < W1_OUT; c += 128) {
                float4 w4 = *(const float4*)(wr + c);
                az = fmaf(w4.x, sh2[c],     az); az = fmaf(w4.y, sh2[c + 1], az);
                az = fmaf(w4.z, sh2[c + 2], az); az = fmaf(w4.w, sh2[c + 3], az);
                ad = fmaf(w4.x, st2[c],     ad); ad = fmaf(w4.y, st2[c + 1], ad);
                ad = fmaf(w4.z, st2[c + 2], ad); ad = fmaf(w4.w, st2[c + 3], ad);
            }
#pragma unroll
            for (int o = 16; o; o >>= 1) {
                az += __shfl_xor_sync(0xffffffffu, az, o);
                ad += __shfl_xor_sync(0xffffffffu, ad, o);
            }
            if (lane == 0) { z[r] = az + we_b2[r]; dz[r] = ad; }
        }
        __syncthreads();

        if (tid < LATENT) { out[tid] = z[tid]; out[LATENT + tid] = dz[tid]; }

        for (int idx = tid; idx < SINDY_DIM; idx += 256) {
            float v;
            if (idx < 16) v = 1.0f;
            else if (idx < 32) v = z[idx - 16];
            else if (idx < 168) {
                int q = idx - 32, i = 0;
                for (;;) { int m = 16 - i; if (q < m) break; q -= m; i++; }
                v = z[i] * z[i + q];
            } else {
                int t = idx - 168, i = 0;
                for (;;) { int m = 16 - i; int c = m * (m + 1) / 2; if (t < c) break; t -= c; i++; }
                int j = i;
                for (;;) { int m = 16 - j; if (t < m) break; t -= m; j++; }
                v = z[i] * z[j] * z[j + t];
            }
            theta[idx] = v;
        }
        __syncthreads();

        for (int r = warp; r < LATENT; r += 8) {
            float a = 0.0f;
            const float* er = E_w + (size_t)r * SINDY_DIM;
            for (int c = lane; c < SINDY_DIM; c += 32)
                a = fmaf(er[c], theta[c], a);
#pragma unroll
            for (int o = 16; o; o >>= 1)
                a += __shfl_xor_sync(0xffffffffu, a, o);
            if (lane == 0) dzb[r] = a + E_b[r];
        }
        __syncthreads();

        if (tid < LATENT) out[32 + tid] = dzb[tid];

        // dec L0 + activation -> g_g1/g_p1
        for (int row = tid; row < 1024; row += 256) {
            float a = wd_b0[row], bb = 0.0f;
            const float* wr = wd_w0 + (size_t)row * LATENT;
#pragma unroll
            for (int c = 0; c < LATENT; c++) {
                float w = wr[c];
                a  = fmaf(w, z[c],   a);
                bb = fmaf(w, dzb[c], bb);
            }
            float s = sigf(a);
            g_g1[row] = s;
            g_p1[row] = s * (1.0f - s) * bb;
        }
        __threadfence();                  // release g_g1/g_p1
        __syncthreads();
        if (tid == 0) g_flag = 1u;
    } else {
        // spin until the small chain publishes g_g1/g_p1
        if (tid == 0) {
            while (g_flag == 0u) { }
        }
        __syncthreads();
        __threadfence();                  // acquire
    }

    // ---- dec L1 matvec (all 1024 blocks, incl. block 0) ----
    dual_body<1024, 1024, 4, 256, false>(
        Wt, g_g1, g_p1, b, g_q2, g_v2, row0);

    // finish ticket: last block resets flag for the next graph replay
    __syncthreads();
    if (tid == 0) {
        unsigned t = atomicAdd(&g_fin, 1u);
        if (t == 1023u) { g_flag = 0u; g_fin = 0u; __threadfence(); }
    }
}

// dec L2 (256 MB, last) — exact R4
__global__ void __launch_bounds__(256) k_dec2(
    const float* __restrict__ W, const float* __restrict__ b,
    float* __restrict__ out)
{
    const int row0 = blockIdx.x * 4;
    const float* Wt = W + (size_t)row0 * 4096;
    prefetch_tile<256>(Wt, 4 * 4096 * 4);
    pdl_wait();
    dual_body<4096, 4096, 4, 256, true>(
        Wt, g_q2, g_v2, b, out + 48, out + 48 + 16384, row0);
}

// ---------------------------------------------------------------------------
extern "C" void kernel_launch(void* const* d_in, const int* in_sizes, int n_in,
                              void* d_out, int out_size)
{
    const float* x     = (const float*)d_in[0];
    const float* dx    = (const float*)d_in[1];
    const float* we_w0 = (const float*)d_in[3];
    const float* we_b0 = (const float*)d_in[4];
    const float* we_w1 = (const float*)d_in[5];
    const float* we_b1 = (const float*)d_in[6];
    const float* we_w2 = (const float*)d_in[7];
    const float* we_b2 = (const float*)d_in[8];
    const float* wd_w0 = (const float*)d_in[9];
    const float* wd_b0 = (const float*)d_in[10];
    const float* wd_w1 = (const float*)d_in[11];
    const float* wd_b1 = (const float*)d_in[12];
    const float* wd_w2 = (const float*)d_in[13];
    const float* wd_b2 = (const float*)d_in[14];
    const float* E_w   = (const float*)d_in[15];
    const float* E_b   = (const float*)d_in[16];
    float* out = (float*)d_out;

    cudaLaunchAttribute attr[1];
    attr[0].id = cudaLaunchAttributeProgrammaticStreamSerialization;
    attr[0].val.programmaticStreamSerializationAllowed = 1;

    cudaLaunchConfig_t cfg{};
    cfg.blockDim = dim3(256, 1, 1);
    cfg.dynamicSmemBytes = 0;
    cfg.stream = 0;
    cfg.attrs = attr;
    cfg.numAttrs = 1;

    // 1) enc L0 (256 MB)
    cfg.gridDim = dim3(W0_OUT / 4, 1, 1);
    cudaLaunchKernelEx(&cfg, k_enc0, we_w0, x, dx, we_b0);

    // 2) enc L1 (16 MB, split-K x2) + small-matrix L2 prefetch
    cfg.gridDim = dim3(W1_OUT / 4, 2, 1);
    cudaLaunchKernelEx(&cfg, k_enc1, we_w1, we_b1, we_w2, E_w, wd_w0);

    // 3) dec L1 (16 MB) with head-fused small chain
    cfg.gridDim = dim3(4096 / 4, 1, 1);
    cudaLaunchKernelEx(&cfg, k_dec1f, wd_w1, wd_b1,
                       we_w2, we_b2, E_w, E_b, wd_w0, wd_b0, out);

    // 4) dec L2 (256 MB)
    cfg.gridDim = dim3(16384 / 4, 1, 1);
    cudaLaunchKernelEx(&cfg, k_dec2, wd_w2, wd_b2, out);
}

// round 15
// speedup vs baseline: 1.5767x; 1.2623x over previous
#include <cuda_runtime.h>

// ---------------------------------------------------------------------------
// SINDy autoencoder forward (batch-1, HBM-bound, ~545MB weights/call).
// Output: [z(16) | dz(16) | dzb(16) | xb(16384) | dxb(16384)] = 32816 f32
// R15 = R4 (best measured: 108.8us), locked in after R5-R14 all regressed
// or were neutral:
//   - 5 kernels, PDL-chained (programmatic stream serialization)
//   - big kernels: ROWS=4 dual matvec, batched LDG.128, evict-first weights
//   - dependents prefetch their weight tiles to L2 before griddepcontrol.wait
//   - middle chain in one 512-thread block with smem-staged weights
// ---------------------------------------------------------------------------

#define W0_OUT 4096
#define W0_IN  16384
#define W1_OUT 1024
#define LATENT 16
#define SINDY_DIM 984

__device__ float g_pre1[W0_OUT], g_u1[W0_OUT];
__device__ float g_pre2p[2 * W1_OUT], g_u2p[2 * W1_OUT];
__device__ float g_g1[1024],  g_p1[1024];
__device__ float g_q2[4096],  g_v2[4096];

__device__ __forceinline__ float sigf(float x) { return 1.0f / (1.0f + __expf(-x)); }
__device__ __forceinline__ float4 ldcs4(const float* p) { return __ldcs((const float4*)p); }

__device__ __forceinline__ void pdl_trigger() {
    asm volatile("griddepcontrol.launch_dependents;" ::: "memory");
}
__device__ __forceinline__ void pdl_wait() {
    asm volatile("griddepcontrol.wait;" ::: "memory");
}
__device__ __forceinline__ void l2_prefetch(const void* p) {
    asm volatile("prefetch.global.L2 [%0];" :: "l"(p));
}
template<int THREADS>
__device__ __forceinline__ void prefetch_tile(const float* base, int bytes) {
    const char* p = (const char*)base;
    for (int off = threadIdx.x * 128; off < bytes; off += THREADS * 128)
        l2_prefetch(p + off);
}

// ---------------------------------------------------------------------------
// Dual matvec over a K-chunk: outA[row]=W@a(+bias), outB[row]=W@b.
// ---------------------------------------------------------------------------
template<int KSTRIDE, int KCHUNK, int ROWS, int THREADS, bool SIG>
__device__ __forceinline__ void dual_body(
    const float* __restrict__ W,
    const float* __restrict__ av,
    const float* __restrict__ bv,
    const float* __restrict__ bias,
    float* __restrict__ outA,
    float* __restrict__ outB,
    int row0)
{
    constexpr int NW = THREADS / 32;
    constexpr int ITERS = KCHUNK / (THREADS * 4);
    const int tid = threadIdx.x;

    float accA[ROWS], accB[ROWS];
#pragma unroll
    for (int r = 0; r < ROWS; r++) { accA[r] = 0.0f; accB[r] = 0.0f; }

#pragma unroll 2
    for (int it = 0; it < ITERS; it++) {
        const int k = (it * THREADS + tid) * 4;
        float4 w4[ROWS];
#pragma unroll
        for (int r = 0; r < ROWS; r++)
            w4[r] = ldcs4(W + (size_t)r * KSTRIDE + k);
        float4 a4 = *(const float4*)(av + k);
        float4 b4 = *(const float4*)(bv + k);
        if (SIG) {
            float s;
            s = sigf(a4.x); b4.x *= s * (1.0f - s); a4.x = s;
            s = sigf(a4.y); b4.y *= s * (1.0f - s); a4.y = s;
            s = sigf(a4.z); b4.z *= s * (1.0f - s); a4.z = s;
            s = sigf(a4.w); b4.w *= s * (1.0f - s); a4.w = s;
        }
#pragma unroll
        for (int r = 0; r < ROWS; r++) {
            accA[r] = fmaf(w4[r].x, a4.x, accA[r]);
            accA[r] = fmaf(w4[r].y, a4.y, accA[r]);
            accA[r] = fmaf(w4[r].z, a4.z, accA[r]);
            accA[r] = fmaf(w4[r].w, a4.w, accA[r]);
            accB[r] = fmaf(w4[r].x, b4.x, accB[r]);
            accB[r] = fmaf(w4[r].y, b4.y, accB[r]);
            accB[r] = fmaf(w4[r].z, b4.z, accB[r]);
            accB[r] = fmaf(w4[r].w, b4.w, accB[r]);
        }
    }

    __shared__ float sA[NW][ROWS], sB[NW][ROWS];
    const int lane = tid & 31, warp = tid >> 5;
#pragma unroll
    for (int r = 0; r < ROWS; r++) {
        float vA = accA[r], vB = accB[r];
#pragma unroll
        for (int o = 16; o; o >>= 1) {
            vA += __shfl_xor_sync(0xffffffffu, vA, o);
            vB += __shfl_xor_sync(0xffffffffu, vB, o);
        }
        if (lane == 0) { sA[warp][r] = vA; sB[warp][r] = vB; }
    }
    __syncthreads();
    if (tid < ROWS) {
        float vA = 0.0f, vB = 0.0f;
#pragma unroll
        for (int w = 0; w < NW; w++) { vA += sA[w][tid]; vB += sB[w][tid]; }
        if (bias) vA += bias[row0 + tid];
        outA[row0 + tid] = vA;
        outB[row0 + tid] = vB;
    }
}

// enc L0 (first in chain; no wait needed)
__global__ void __launch_bounds__(256) k_enc0(
    const float* __restrict__ W, const float* __restrict__ x,
    const float* __restrict__ dx, const float* __restrict__ b)
{
    pdl_trigger();
    const int row0 = blockIdx.x * 4;
    pdl_wait();   // no-op vs stream order; keeps pattern uniform
    dual_body<W0_IN, W0_IN, 4, 256, false>(
        W + (size_t)row0 * W0_IN, x, dx, b, g_pre1, g_u1, row0);
}

// enc L1, split-K x2
__global__ void __launch_bounds__(256) k_enc1(
    const float* __restrict__ W, const float* __restrict__ b)
{
    pdl_trigger();
    const int row0  = blockIdx.x * 4;
    const int split = blockIdx.y;
    const int koff  = split * 2048;
    const float* Wt = W + (size_t)row0 * W0_OUT + koff;
    // prefetch 4 rows x 2048 f = 4 x 8KB (rows not contiguous due to split)
#pragma unroll
    for (int r = 0; r < 4; r++)
        prefetch_tile<256>(Wt + (size_t)r * W0_OUT, 8192);
    pdl_wait();
    dual_body<W0_OUT, 2048, 4, 256, true>(
        Wt, g_pre1 + koff, g_u1 + koff,
        split == 0 ? b : nullptr,
        g_pre2p + split * W1_OUT, g_u2p + split * W1_OUT, row0);
}

// dec L1
__global__ void __launch_bounds__(256) k_dec1(
    const float* __restrict__ W, const float* __restrict__ b)
{
    pdl_trigger();
    const int row0 = blockIdx.x * 4;
    const float* Wt = W + (size_t)row0 * 1024;
    prefetch_tile<256>(Wt, 4 * 1024 * 4);   // 16 KB contiguous
    pdl_wait();
    dual_body<1024, 1024, 4, 256, false>(
        Wt, g_g1, g_p1, b, g_q2, g_v2, row0);
}

// dec L2 (last; writes final outputs)
__global__ void __launch_bounds__(256) k_dec2(
    const float* __restrict__ W, const float* __restrict__ b,
    float* __restrict__ out)
{
    const int row0 = blockIdx.x * 4;
    const float* Wt = W + (size_t)row0 * 4096;
    prefetch_tile<256>(Wt, 4 * 4096 * 4);   // 64 KB contiguous
    pdl_wait();
    dual_body<4096, 4096, 4, 256, true>(
        Wt, g_q2, g_v2, b, out + 48, out + 48 + 16384, row0);
}

// ---------------------------------------------------------------------------
// Middle chain, one block, 512 threads, weights prefetched to smem.
// ---------------------------------------------------------------------------
#define SM_WE2   0
#define SM_EW    16384
#define SM_WD0   32128
#define SM_H2    48512
#define SM_T2    49536
#define SM_THETA 50560
#define SM_FLOATS 51544
#define SM_BYTES (SM_FLOATS * 4)

__global__ void __launch_bounds__(512) k_small(
    const float* __restrict__ we_w2, const float* __restrict__ we_b2,
    const float* __restrict__ E_w,   const float* __restrict__ E_b,
    const float* __restrict__ wd_w0, const float* __restrict__ wd_b0,
    float* __restrict__ out)
{
    extern __shared__ float sm[];
    __shared__ float z[LATENT], dz[LATENT], dzb[LATENT];

    const int tid = threadIdx.x;
    const int lane = tid & 31, wid = tid >> 5;

    pdl_trigger();
    prefetch_tile<512>(we_w2, 16384 * 4);
    prefetch_tile<512>(E_w,   15744 * 4);
    prefetch_tile<512>(wd_w0, 16384 * 4);
    pdl_wait();

    for (int i = tid; i < 4096; i += 512)
        *(float4*)(sm + SM_WE2 + i * 4) = ldcs4(we_w2 + i * 4);
    for (int i = tid; i < 3936; i += 512)
        *(float4*)(sm + SM_EW + i * 4) = ldcs4(E_w + i * 4);
    for (int i = tid; i < 4096; i += 512)
        *(float4*)(sm + SM_WD0 + i * 4) = ldcs4(wd_w0 + i * 4);
    for (int i = tid; i < W1_OUT; i += 512) {
        float pre = g_pre2p[i] + g_pre2p[W1_OUT + i];
        float u   = g_u2p[i]   + g_u2p[W1_OUT + i];
        float s = sigf(pre);
        sm[SM_H2 + i] = s;
        sm[SM_T2 + i] = s * (1.0f - s) * u;
    }
    __syncthreads();

    {
        float az = 0.0f, ad = 0.0f;
        const float* wr = sm + SM_WE2 + wid * W1_OUT;
        for (int c = lane; c < W1_OUT; c += 32) {
            float w = wr[c];
            az = fmaf(w, sm[SM_H2 + c], az);
            ad = fmaf(w, sm[SM_T2 + c], ad);
        }
#pragma unroll
        for (int o = 16; o; o >>= 1) {
            az += __shfl_xor_sync(0xffffffffu, az, o);
            ad += __shfl_xor_sync(0xffffffffu, ad, o);
        }
        if (lane == 0) { z[wid] = az + we_b2[wid]; dz[wid] = ad; }
    }
    __syncthreads();

    if (tid < LATENT) { out[tid] = z[tid]; out[LATENT + tid] = dz[tid]; }

    for (int idx = tid; idx < SINDY_DIM; idx += 512) {
        float v;
        if (idx < 16) v = 1.0f;
        else if (idx < 32) v = z[idx - 16];
        else if (idx < 168) {
            int q = idx - 32, i = 0;
            for (;;) { int m = 16 - i; if (q < m) break; q -= m; i++; }
            v = z[i] * z[i + q];
        } else {
            int t = idx - 168, i = 0;
            for (;;) { int m = 16 - i; int c = m * (m + 1) / 2; if (t < c) break; t -= c; i++; }
            int j = i;
            for (;;) { int m = 16 - j; if (t < m) break; t -= m; j++; }
            v = z[i] * z[j] * z[j + t];
        }
        sm[SM_THETA + idx] = v;
    }
    __syncthreads();

    {
        float a = 0.0f;
        const float* er = sm + SM_EW + wid * SINDY_DIM;
        for (int c = lane; c < SINDY_DIM; c += 32)
            a = fmaf(er[c], sm[SM_THETA + c], a);
#pragma unroll
        for (int o = 16; o; o >>= 1)
            a += __shfl_xor_sync(0xffffffffu, a, o);
        if (lane == 0) dzb[wid] = a + E_b[wid];
    }
    __syncthreads();

    if (tid < LATENT) out[32 + tid] = dzb[tid];

    for (int row = tid; row < 1024; row += 512) {
        float a = wd_b0[row], bb = 0.0f;
        const float* wr = sm + SM_WD0 + row * LATENT;
#pragma unroll
        for (int c = 0; c < LATENT; c++) {
            float w = wr[c];
            a  = fmaf(w, z[c],   a);
            bb = fmaf(w, dzb[c], bb);
        }
        float s = sigf(a);
        g_g1[row] = s;
        g_p1[row] = s * (1.0f - s) * bb;
    }
}

// ---------------------------------------------------------------------------
extern "C" void kernel_launch(void* const* d_in, const int* in_sizes, int n_in,
                              void* d_out, int out_size)
{
    const float* x     = (const float*)d_in[0];
    const float* dx    = (const float*)d_in[1];
    const float* we_w0 = (const float*)d_in[3];
    const float* we_b0 = (const float*)d_in[4];
    const float* we_w1 = (const float*)d_in[5];
    const float* we_b1 = (const float*)d_in[6];
    const float* we_w2 = (const float*)d_in[7];
    const float* we_b2 = (const float*)d_in[8];
    const float* wd_w0 = (const float*)d_in[9];
    const float* wd_b0 = (const float*)d_in[10];
    const float* wd_w1 = (const float*)d_in[11];
    const float* wd_b1 = (const float*)d_in[12];
    const float* wd_w2 = (const float*)d_in[13];
    const float* wd_b2 = (const float*)d_in[14];
    const float* E_w   = (const float*)d_in[15];
    const float* E_b   = (const float*)d_in[16];
    float* out = (float*)d_out;

    cudaFuncSetAttribute(k_small, cudaFuncAttributeMaxDynamicSharedMemorySize, SM_BYTES);

    cudaLaunchAttribute attr[1];
    attr[0].id = cudaLaunchAttributeProgrammaticStreamSerialization;
    attr[0].val.programmaticStreamSerializationAllowed = 1;

    cudaLaunchConfig_t cfg{};
    cfg.blockDim = dim3(256, 1, 1);
    cfg.dynamicSmemBytes = 0;
    cfg.stream = 0;
    cfg.attrs = attr;
    cfg.numAttrs = 1;

    // 1) enc L0 (256 MB)
    cfg.gridDim = dim3(W0_OUT / 4, 1, 1);
    cudaLaunchKernelEx(&cfg, k_enc0, we_w0, x, dx, we_b0);

    // 2) enc L1 (16 MB, split-K x2)
    cfg.gridDim = dim3(W1_OUT / 4, 2, 1);
    cudaLaunchKernelEx(&cfg, k_enc1, we_w1, we_b1);

    // 3) middle chain
    {
        cudaLaunchConfig_t cs = cfg;
        cs.gridDim = dim3(1, 1, 1);
        cs.blockDim = dim3(512, 1, 1);
        cs.dynamicSmemBytes = SM_BYTES;
        cudaLaunchKernelEx(&cs, k_small, we_w2, we_b2, E_w, E_b, wd_w0, wd_b0, out);
    }

    // 4) dec L1 (16 MB)
    cfg.gridDim = dim3(4096 / 4, 1, 1);
    cudaLaunchKernelEx(&cfg, k_dec1, wd_w1, wd_b1);

    // 5) dec L2 (256 MB)
    cfg.gridDim = dim3(16384 / 4, 1, 1);
    cudaLaunchKernelEx(&cfg, k_dec2, wd_w2, wd_b2, out);
}

// round 16
// speedup vs baseline: 1.5865x; 1.0062x over previous
#include <cuda_runtime.h>

// ---------------------------------------------------------------------------
// SINDy autoencoder forward (batch-1, HBM-bound, ~545MB weights/call).
// Output: [z(16) | dz(16) | dzb(16) | xb(16384) | dxb(16384)] = 32816 f32
// R16 = R4 (measured best 108.8us) + ONE isolated addition: enc1 block (0,0)
//       prefetches k_small's three small weight matrices (~190KB) into L2
//       during its pre-wait window, so k_small's smem staging hits L2.
// Everything else is byte-for-byte the R4 plateau configuration:
//   - 5 kernels, PDL-chained (programmatic stream serialization)
//   - big kernels: ROWS=4 dual matvec, batched LDG.128, evict-first weights
//   - dependents prefetch their own weight tiles before griddepcontrol.wait
//   - middle chain in one 512-thread block with smem-staged weights
// ---------------------------------------------------------------------------

#define W0_OUT 4096
#define W0_IN  16384
#define W1_OUT 1024
#define LATENT 16
#define SINDY_DIM 984

__device__ float g_pre1[W0_OUT], g_u1[W0_OUT];
__device__ float g_pre2p[2 * W1_OUT], g_u2p[2 * W1_OUT];
__device__ float g_g1[1024],  g_p1[1024];
__device__ float g_q2[4096],  g_v2[4096];

__device__ __forceinline__ float sigf(float x) { return 1.0f / (1.0f + __expf(-x)); }
__device__ __forceinline__ float4 ldcs4(const float* p) { return __ldcs((const float4*)p); }

__device__ __forceinline__ void pdl_trigger() {
    asm volatile("griddepcontrol.launch_dependents;" ::: "memory");
}
__device__ __forceinline__ void pdl_wait() {
    asm volatile("griddepcontrol.wait;" ::: "memory");
}
__device__ __forceinline__ void l2_prefetch(const void* p) {
    asm volatile("prefetch.global.L2 [%0];" :: "l"(p));
}
template<int THREADS>
__device__ __forceinline__ void prefetch_tile(const float* base, int bytes) {
    const char* p = (const char*)base;
    for (int off = threadIdx.x * 128; off < bytes; off += THREADS * 128)
        l2_prefetch(p + off);
}

// ---------------------------------------------------------------------------
// Dual matvec over a K-chunk: outA[row]=W@a(+bias), outB[row]=W@b.
// ---------------------------------------------------------------------------
template<int KSTRIDE, int KCHUNK, int ROWS, int THREADS, bool SIG>
__device__ __forceinline__ void dual_body(
    const float* __restrict__ W,
    const float* __restrict__ av,
    const float* __restrict__ bv,
    const float* __restrict__ bias,
    float* __restrict__ outA,
    float* __restrict__ outB,
    int row0)
{
    constexpr int NW = THREADS / 32;
    constexpr int ITERS = KCHUNK / (THREADS * 4);
    const int tid = threadIdx.x;

    float accA[ROWS], accB[ROWS];
#pragma unroll
    for (int r = 0; r < ROWS; r++) { accA[r] = 0.0f; accB[r] = 0.0f; }

#pragma unroll 2
    for (int it = 0; it < ITERS; it++) {
        const int k = (it * THREADS + tid) * 4;
        float4 w4[ROWS];
#pragma unroll
        for (int r = 0; r < ROWS; r++)
            w4[r] = ldcs4(W + (size_t)r * KSTRIDE + k);
        float4 a4 = *(const float4*)(av + k);
        float4 b4 = *(const float4*)(bv + k);
        if (SIG) {
            float s;
            s = sigf(a4.x); b4.x *= s * (1.0f - s); a4.x = s;
            s = sigf(a4.y); b4.y *= s * (1.0f - s); a4.y = s;
            s = sigf(a4.z); b4.z *= s * (1.0f - s); a4.z = s;
            s = sigf(a4.w); b4.w *= s * (1.0f - s); a4.w = s;
        }
#pragma unroll
        for (int r = 0; r < ROWS; r++) {
            accA[r] = fmaf(w4[r].x, a4.x, accA[r]);
            accA[r] = fmaf(w4[r].y, a4.y, accA[r]);
            accA[r] = fmaf(w4[r].z, a4.z, accA[r]);
            accA[r] = fmaf(w4[r].w, a4.w, accA[r]);
            accB[r] = fmaf(w4[r].x, b4.x, accB[r]);
            accB[r] = fmaf(w4[r].y, b4.y, accB[r]);
            accB[r] = fmaf(w4[r].z, b4.z, accB[r]);
            accB[r] = fmaf(w4[r].w, b4.w, accB[r]);
        }
    }

    __shared__ float sA[NW][ROWS], sB[NW][ROWS];
    const int lane = tid & 31, warp = tid >> 5;
#pragma unroll
    for (int r = 0; r < ROWS; r++) {
        float vA = accA[r], vB = accB[r];
#pragma unroll
        for (int o = 16; o; o >>= 1) {
            vA += __shfl_xor_sync(0xffffffffu, vA, o);
            vB += __shfl_xor_sync(0xffffffffu, vB, o);
        }
        if (lane == 0) { sA[warp][r] = vA; sB[warp][r] = vB; }
    }
    __syncthreads();
    if (tid < ROWS) {
        float vA = 0.0f, vB = 0.0f;
#pragma unroll
        for (int w = 0; w < NW; w++) { vA += sA[w][tid]; vB += sB[w][tid]; }
        if (bias) vA += bias[row0 + tid];
        outA[row0 + tid] = vA;
        outB[row0 + tid] = vB;
    }
}

// enc L0 (first in chain)
__global__ void __launch_bounds__(256) k_enc0(
    const float* __restrict__ W, const float* __restrict__ x,
    const float* __restrict__ dx, const float* __restrict__ b)
{
    pdl_trigger();
    const int row0 = blockIdx.x * 4;
    pdl_wait();
    dual_body<W0_IN, W0_IN, 4, 256, false>(
        W + (size_t)row0 * W0_IN, x, dx, b, g_pre1, g_u1, row0);
}

// enc L1, split-K x2 + small-matrix L2 prefetch from block (0,0) only
__global__ void __launch_bounds__(256) k_enc1(
    const float* __restrict__ W, const float* __restrict__ b,
    const float* __restrict__ we_w2, const float* __restrict__ E_w,
    const float* __restrict__ wd_w0)
{
    pdl_trigger();
    const int row0  = blockIdx.x * 4;
    const int split = blockIdx.y;
    const int koff  = split * 2048;
    const float* Wt = W + (size_t)row0 * W0_OUT + koff;
#pragma unroll
    for (int r = 0; r < 4; r++)
        prefetch_tile<256>(Wt + (size_t)r * W0_OUT, 8192);
    if (blockIdx.x == 0 && split == 0) {
        // ~190KB for k_small, issued in the pre-wait window (benign, isolated)
        prefetch_tile<256>(we_w2, 16384 * 4);
        prefetch_tile<256>(E_w,   15744 * 4);
        prefetch_tile<256>(wd_w0, 16384 * 4);
    }
    pdl_wait();
    dual_body<W0_OUT, 2048, 4, 256, true>(
        Wt, g_pre1 + koff, g_u1 + koff,
        split == 0 ? b : nullptr,
        g_pre2p + split * W1_OUT, g_u2p + split * W1_OUT, row0);
}

// dec L1
__global__ void __launch_bounds__(256) k_dec1(
    const float* __restrict__ W, const float* __restrict__ b)
{
    pdl_trigger();
    const int row0 = blockIdx.x * 4;
    const float* Wt = W + (size_t)row0 * 1024;
    prefetch_tile<256>(Wt, 4 * 1024 * 4);
    pdl_wait();
    dual_body<1024, 1024, 4, 256, false>(
        Wt, g_g1, g_p1, b, g_q2, g_v2, row0);
}

// dec L2 (last; writes final outputs)
__global__ void __launch_bounds__(256) k_dec2(
    const float* __restrict__ W, const float* __restrict__ b,
    float* __restrict__ out)
{
    const int row0 = blockIdx.x * 4;
    const float* Wt = W + (size_t)row0 * 4096;
    prefetch_tile<256>(Wt, 4 * 4096 * 4);
    pdl_wait();
    dual_body<4096, 4096, 4, 256, true>(
        Wt, g_q2, g_v2, b, out + 48, out + 48 + 16384, row0);
}

// ---------------------------------------------------------------------------
// Middle chain, one block, 512 threads, weights staged to smem (L2-hot now).
// ---------------------------------------------------------------------------
#define SM_WE2   0
#define SM_EW    16384
#define SM_WD0   32128
#define SM_H2    48512
#define SM_T2    49536
#define SM_THETA 50560
#define SM_FLOATS 51544
#define SM_BYTES (SM_FLOATS * 4)

__global__ void __launch_bounds__(512) k_small(
    const float* __restrict__ we_w2, const float* __restrict__ we_b2,
    const float* __restrict__ E_w,   const float* __restrict__ E_b,
    const float* __restrict__ wd_w0, const float* __restrict__ wd_b0,
    float* __restrict__ out)
{
    extern __shared__ float sm[];
    __shared__ float z[LATENT], dz[LATENT], dzb[LATENT];

    const int tid = threadIdx.x;
    const int lane = tid & 31, wid = tid >> 5;

    pdl_trigger();
    prefetch_tile<512>(we_w2, 16384 * 4);
    prefetch_tile<512>(E_w,   15744 * 4);
    prefetch_tile<512>(wd_w0, 16384 * 4);
    pdl_wait();

    for (int i = tid; i < 4096; i += 512)
        *(float4*)(sm + SM_WE2 + i * 4) = ldcs4(we_w2 + i * 4);
    for (int i = tid; i < 3936; i += 512)
        *(float4*)(sm + SM_EW + i * 4) = ldcs4(E_w + i * 4);
    for (int i = tid; i < 4096; i += 512)
        *(float4*)(sm + SM_WD0 + i * 4) = ldcs4(wd_w0 + i * 4);
    for (int i = tid; i < W1_OUT; i += 512) {
        float pre = g_pre2p[i] + g_pre2p[W1_OUT + i];
        float u   = g_u2p[i]   + g_u2p[W1_OUT + i];
        float s = sigf(pre);
        sm[SM_H2 + i] = s;
        sm[SM_T2 + i] = s * (1.0f - s) * u;
    }
    __syncthreads();

    {
        float az = 0.0f, ad = 0.0f;
        const float* wr = sm + SM_WE2 + wid * W1_OUT;
        for (int c = lane; c < W1_OUT; c += 32) {
            float w = wr[c];
            az = fmaf(w, sm[SM_H2 + c], az);
            ad = fmaf(w, sm[SM_T2 + c], ad);
        }
#pragma unroll
        for (int o = 16; o; o >>= 1) {
            az += __shfl_xor_sync(0xffffffffu, az, o);
            ad += __shfl_xor_sync(0xffffffffu, ad, o);
        }
        if (lane == 0) { z[wid] = az + we_b2[wid]; dz[wid] = ad; }
    }
    __syncthreads();

    if (tid < LATENT) { out[tid] = z[tid]; out[LATENT + tid] = dz[tid]; }

    for (int idx = tid; idx < SINDY_DIM; idx += 512) {
        float v;
        if (idx < 16) v = 1.0f;
        else if (idx < 32) v = z[idx - 16];
        else if (idx < 168) {
            int q = idx - 32, i = 0;
            for (;;) { int m = 16 - i; if (q < m) break; q -= m; i++; }
            v = z[i] * z[i + q];
        } else {
            int t = idx - 168, i = 0;
            for (;;) { int m = 16 - i; int c = m * (m + 1) / 2; if (t < c) break; t -= c; i++; }
            int j = i;
            for (;;) { int m = 16 - j; if (t < m) break; t -= m; j++; }
            v = z[i] * z[j] * z[j + t];
        }
        sm[SM_THETA + idx] = v;
    }
    __syncthreads();

    {
        float a = 0.0f;
        const float* er = sm + SM_EW + wid * SINDY_DIM;
        for (int c = lane; c < SINDY_DIM; c += 32)
            a = fmaf(er[c], sm[SM_THETA + c], a);
#pragma unroll
        for (int o = 16; o; o >>= 1)
            a += __shfl_xor_sync(0xffffffffu, a, o);
        if (lane == 0) dzb[wid] = a + E_b[wid];
    }
    __syncthreads();

    if (tid < LATENT) out[32 + tid] = dzb[tid];

    for (int row = tid; row < 1024; row += 512) {
        float a = wd_b0[row], bb = 0.0f;
        const float* wr = sm + SM_WD0 + row * LATENT;
#pragma unroll
        for (int c = 0; c < LATENT; c++) {
            float w = wr[c];
            a  = fmaf(w, z[c],   a);
            bb = fmaf(w, dzb[c], bb);
        }
        float s = sigf(a);
        g_g1[row] = s;
        g_p1[row] = s * (1.0f - s) * bb;
    }
}

// ---------------------------------------------------------------------------
extern "C" void kernel_launch(void* const* d_in, const int* in_sizes, int n_in,
                              void* d_out, int out_size)
{
    const float* x     = (const float*)d_in[0];
    const float* dx    = (const float*)d_in[1];
    const float* we_w0 = (const float*)d_in[3];
    const float* we_b0 = (const float*)d_in[4];
    const float* we_w1 = (const float*)d_in[5];
    const float* we_b1 = (const float*)d_in[6];
    const float* we_w2 = (const float*)d_in[7];
    const float* we_b2 = (const float*)d_in[8];
    const float* wd_w0 = (const float*)d_in[9];
    const float* wd_b0 = (const float*)d_in[10];
    const float* wd_w1 = (const float*)d_in[11];
    const float* wd_b1 = (const float*)d_in[12];
    const float* wd_w2 = (const float*)d_in[13];
    const float* wd_b2 = (const float*)d_in[14];
    const float* E_w   = (const float*)d_in[15];
    const float* E_b   = (const float*)d_in[16];
    float* out = (float*)d_out;

    cudaFuncSetAttribute(k_small, cudaFuncAttributeMaxDynamicSharedMemorySize, SM_BYTES);

    cudaLaunchAttribute attr[1];
    attr[0].id = cudaLaunchAttributeProgrammaticStreamSerialization;
    attr[0].val.programmaticStreamSerializationAllowed = 1;

    cudaLaunchConfig_t cfg{};
    cfg.blockDim = dim3(256, 1, 1);
    cfg.dynamicSmemBytes = 0;
    cfg.stream = 0;
    cfg.attrs = attr;
    cfg.numAttrs = 1;

    // 1) enc L0 (256 MB)
    cfg.gridDim = dim3(W0_OUT / 4, 1, 1);
    cudaLaunchKernelEx(&cfg, k_enc0, we_w0, x, dx, we_b0);

    // 2) enc L1 (16 MB, split-K x2) + small-matrix L2 prefetch
    cfg.gridDim = dim3(W1_OUT / 4, 2, 1);
    cudaLaunchKernelEx(&cfg, k_enc1, we_w1, we_b1, we_w2, E_w, wd_w0);

    // 3) middle chain
    {
        cudaLaunchConfig_t cs = cfg;
        cs.gridDim = dim3(1, 1, 1);
        cs.blockDim = dim3(512, 1, 1);
        cs.dynamicSmemBytes = SM_BYTES;
        cudaLaunchKernelEx(&cs, k_small, we_w2, we_b2, E_w, E_b, wd_w0, wd_b0, out);
    }

    // 4) dec L1 (16 MB)
    cfg.gridDim = dim3(4096 / 4, 1, 1);
    cudaLaunchKernelEx(&cfg, k_dec1, wd_w1, wd_b1);

    // 5) dec L2 (256 MB)
    cfg.gridDim = dim3(16384 / 4, 1, 1);
    cudaLaunchKernelEx(&cfg, k_dec2, wd_w2, wd_b2, out);
}

// round 17
// speedup vs baseline: 1.5897x; 1.0021x over previous
#include <cuda_runtime.h>

// ---------------------------------------------------------------------------
// SINDy autoencoder forward (batch-1, HBM-bound, ~545MB weights/call).
// Output: [z(16) | dz(16) | dzb(16) | xb(16384) | dxb(16384)] = 32816 f32
// R17 = R16 (measured best 108.64us) + k_small reads its single-use weight
//       matrices (we_w2, E_w, wd_w0) DIRECTLY from L2-hot global instead of
//       staging 190KB through smem first (each row is consumed exactly once).
//       h2/t2 and theta (multi-warp reuse) stay in smem.
// ---------------------------------------------------------------------------

#define W0_OUT 4096
#define W0_IN  16384
#define W1_OUT 1024
#define LATENT 16
#define SINDY_DIM 984

__device__ float g_pre1[W0_OUT], g_u1[W0_OUT];
__device__ float g_pre2p[2 * W1_OUT], g_u2p[2 * W1_OUT];
__device__ float g_g1[1024],  g_p1[1024];
__device__ float g_q2[4096],  g_v2[4096];

__device__ __forceinline__ float sigf(float x) { return 1.0f / (1.0f + __expf(-x)); }
__device__ __forceinline__ float4 ldcs4(const float* p) { return __ldcs((const float4*)p); }

__device__ __forceinline__ void pdl_trigger() {
    asm volatile("griddepcontrol.launch_dependents;" ::: "memory");
}
__device__ __forceinline__ void pdl_wait() {
    asm volatile("griddepcontrol.wait;" ::: "memory");
}
__device__ __forceinline__ void l2_prefetch(const void* p) {
    asm volatile("prefetch.global.L2 [%0];" :: "l"(p));
}
template<int THREADS>
__device__ __forceinline__ void prefetch_tile(const float* base, int bytes) {
    const char* p = (const char*)base;
    for (int off = threadIdx.x * 128; off < bytes; off += THREADS * 128)
        l2_prefetch(p + off);
}

// ---------------------------------------------------------------------------
// Dual matvec over a K-chunk: outA[row]=W@a(+bias), outB[row]=W@b.
// ---------------------------------------------------------------------------
template<int KSTRIDE, int KCHUNK, int ROWS, int THREADS, bool SIG>
__device__ __forceinline__ void dual_body(
    const float* __restrict__ W,
    const float* __restrict__ av,
    const float* __restrict__ bv,
    const float* __restrict__ bias,
    float* __restrict__ outA,
    float* __restrict__ outB,
    int row0)
{
    constexpr int NW = THREADS / 32;
    constexpr int ITERS = KCHUNK / (THREADS * 4);
    const int tid = threadIdx.x;

    float accA[ROWS], accB[ROWS];
#pragma unroll
    for (int r = 0; r < ROWS; r++) { accA[r] = 0.0f; accB[r] = 0.0f; }

#pragma unroll 2
    for (int it = 0; it < ITERS; it++) {
        const int k = (it * THREADS + tid) * 4;
        float4 w4[ROWS];
#pragma unroll
        for (int r = 0; r < ROWS; r++)
            w4[r] = ldcs4(W + (size_t)r * KSTRIDE + k);
        float4 a4 = *(const float4*)(av + k);
        float4 b4 = *(const float4*)(bv + k);
        if (SIG) {
            float s;
            s = sigf(a4.x); b4.x *= s * (1.0f - s); a4.x = s;
            s = sigf(a4.y); b4.y *= s * (1.0f - s); a4.y = s;
            s = sigf(a4.z); b4.z *= s * (1.0f - s); a4.z = s;
            s = sigf(a4.w); b4.w *= s * (1.0f - s); a4.w = s;
        }
#pragma unroll
        for (int r = 0; r < ROWS; r++) {
            accA[r] = fmaf(w4[r].x, a4.x, accA[r]);
            accA[r] = fmaf(w4[r].y, a4.y, accA[r]);
            accA[r] = fmaf(w4[r].z, a4.z, accA[r]);
            accA[r] = fmaf(w4[r].w, a4.w, accA[r]);
            accB[r] = fmaf(w4[r].x, b4.x, accB[r]);
            accB[r] = fmaf(w4[r].y, b4.y, accB[r]);
            accB[r] = fmaf(w4[r].z, b4.z, accB[r]);
            accB[r] = fmaf(w4[r].w, b4.w, accB[r]);
        }
    }

    __shared__ float sA[NW][ROWS], sB[NW][ROWS];
    const int lane = tid & 31, warp = tid >> 5;
#pragma unroll
    for (int r = 0; r < ROWS; r++) {
        float vA = accA[r], vB = accB[r];
#pragma unroll
        for (int o = 16; o; o >>= 1) {
            vA += __shfl_xor_sync(0xffffffffu, vA, o);
            vB += __shfl_xor_sync(0xffffffffu, vB, o);
        }
        if (lane == 0) { sA[warp][r] = vA; sB[warp][r] = vB; }
    }
    __syncthreads();
    if (tid < ROWS) {
        float vA = 0.0f, vB = 0.0f;
#pragma unroll
        for (int w = 0; w < NW; w++) { vA += sA[w][tid]; vB += sB[w][tid]; }
        if (bias) vA += bias[row0 + tid];
        outA[row0 + tid] = vA;
        outB[row0 + tid] = vB;
    }
}

// enc L0 (first in chain)
__global__ void __launch_bounds__(256) k_enc0(
    const float* __restrict__ W, const float* __restrict__ x,
    const float* __restrict__ dx, const float* __restrict__ b)
{
    pdl_trigger();
    const int row0 = blockIdx.x * 4;
    pdl_wait();
    dual_body<W0_IN, W0_IN, 4, 256, false>(
        W + (size_t)row0 * W0_IN, x, dx, b, g_pre1, g_u1, row0);
}

// enc L1, split-K x2 + small-matrix L2 prefetch from block (0,0) (R16)
__global__ void __launch_bounds__(256) k_enc1(
    const float* __restrict__ W, const float* __restrict__ b,
    const float* __restrict__ we_w2, const float* __restrict__ E_w,
    const float* __restrict__ wd_w0)
{
    pdl_trigger();
    const int row0  = blockIdx.x * 4;
    const int split = blockIdx.y;
    const int koff  = split * 2048;
    const float* Wt = W + (size_t)row0 * W0_OUT + koff;
#pragma unroll
    for (int r = 0; r < 4; r++)
        prefetch_tile<256>(Wt + (size_t)r * W0_OUT, 8192);
    if (blockIdx.x == 0 && split == 0) {
        prefetch_tile<256>(we_w2, 16384 * 4);
        prefetch_tile<256>(E_w,   15744 * 4);
        prefetch_tile<256>(wd_w0, 16384 * 4);
    }
    pdl_wait();
    dual_body<W0_OUT, 2048, 4, 256, true>(
        Wt, g_pre1 + koff, g_u1 + koff,
        split == 0 ? b : nullptr,
        g_pre2p + split * W1_OUT, g_u2p + split * W1_OUT, row0);
}

// dec L1
__global__ void __launch_bounds__(256) k_dec1(
    const float* __restrict__ W, const float* __restrict__ b)
{
    pdl_trigger();
    const int row0 = blockIdx.x * 4;
    const float* Wt = W + (size_t)row0 * 1024;
    prefetch_tile<256>(Wt, 4 * 1024 * 4);
    pdl_wait();
    dual_body<1024, 1024, 4, 256, false>(
        Wt, g_g1, g_p1, b, g_q2, g_v2, row0);
}

// dec L2 (last; writes final outputs)
__global__ void __launch_bounds__(256) k_dec2(
    const float* __restrict__ W, const float* __restrict__ b,
    float* __restrict__ out)
{
    const int row0 = blockIdx.x * 4;
    const float* Wt = W + (size_t)row0 * 4096;
    prefetch_tile<256>(Wt, 4 * 4096 * 4);
    pdl_wait();
    dual_body<4096, 4096, 4, 256, true>(
        Wt, g_q2, g_v2, b, out + 48, out + 48 + 16384, row0);
}

// ---------------------------------------------------------------------------
// Middle chain, one block, 512 threads. Weights read DIRECTLY from L2-hot
// global (single-use rows); only reused vectors (h2/t2, theta) live in smem.
// ---------------------------------------------------------------------------
__global__ void __launch_bounds__(512) k_small(
    const float* __restrict__ we_w2, const float* __restrict__ we_b2,
    const float* __restrict__ E_w,   const float* __restrict__ E_b,
    const float* __restrict__ wd_w0, const float* __restrict__ wd_b0,
    float* __restrict__ out)
{
    __shared__ float sh2[W1_OUT], st2[W1_OUT];
    __shared__ float theta[SINDY_DIM];
    __shared__ float z[LATENT], dz[LATENT], dzb[LATENT];

    const int tid = threadIdx.x;
    const int lane = tid & 31, wid = tid >> 5;   // 16 warps

    pdl_trigger();
    // issue L2 prefetch for own weights (mostly already hot from enc1 b(0,0))
    prefetch_tile<512>(we_w2, 16384 * 4);
    prefetch_tile<512>(E_w,   15744 * 4);
    prefetch_tile<512>(wd_w0, 16384 * 4);
    pdl_wait();

    // h2/t2 from enc1 partials (reused by all warps -> smem)
    for (int i = tid; i < W1_OUT; i += 512) {
        float pre = g_pre2p[i] + g_pre2p[W1_OUT + i];
        float u   = g_u2p[i]   + g_u2p[W1_OUT + i];
        float s = sigf(pre);
        sh2[i] = s;
        st2[i] = s * (1.0f - s) * u;
    }
    __syncthreads();

    // z, dz: warp per row, we_w2 row read once, directly from global (float4)
    {
        float az = 0.0f, ad = 0.0f;
        const float* wr = we_w2 + (size_t)wid * W1_OUT;
        for (int c = lane * 4; c < W1_OUT; c += 128) {
            float4 w4 = *(const float4*)(wr + c);
            az = fmaf(w4.x, sh2[c],     az); az = fmaf(w4.y, sh2[c + 1], az);
            az = fmaf(w4.z, sh2[c + 2], az); az = fmaf(w4.w, sh2[c + 3], az);
            ad = fmaf(w4.x, st2[c],     ad); ad = fmaf(w4.y, st2[c + 1], ad);
            ad = fmaf(w4.z, st2[c + 2], ad); ad = fmaf(w4.w, st2[c + 3], ad);
        }
#pragma unroll
        for (int o = 16; o; o >>= 1) {
            az += __shfl_xor_sync(0xffffffffu, az, o);
            ad += __shfl_xor_sync(0xffffffffu, ad, o);
        }
        if (lane == 0) { z[wid] = az + we_b2[wid]; dz[wid] = ad; }
    }
    __syncthreads();

    if (tid < LATENT) { out[tid] = z[tid]; out[LATENT + tid] = dz[tid]; }

    // theta (reused by all warps -> smem)
    for (int idx = tid; idx < SINDY_DIM; idx += 512) {
        float v;
        if (idx < 16) v = 1.0f;
        else if (idx < 32) v = z[idx - 16];
        else if (idx < 168) {
            int q = idx - 32, i = 0;
            for (;;) { int m = 16 - i; if (q < m) break; q -= m; i++; }
            v = z[i] * z[i + q];
        } else {
            int t = idx - 168, i = 0;
            for (;;) { int m = 16 - i; int c = m * (m + 1) / 2; if (t < c) break; t -= c; i++; }
            int j = i;
            for (;;) { int m = 16 - j; if (t < m) break; t -= m; j++; }
            v = z[i] * z[j] * z[j + t];
        }
        theta[idx] = v;
    }
    __syncthreads();

    // dzb: warp per row, E_w row read once, directly from global
    {
        float a = 0.0f;
        const float* er = E_w + (size_t)wid * SINDY_DIM;
        for (int c = lane; c < SINDY_DIM; c += 32)
            a = fmaf(er[c], theta[c], a);
#pragma unroll
        for (int o = 16; o; o >>= 1)
            a += __shfl_xor_sync(0xffffffffu, a, o);
        if (lane == 0) dzb[wid] = a + E_b[wid];
    }
    __syncthreads();

    if (tid < LATENT) out[32 + tid] = dzb[tid];

    // dec L0 + activation: each wd_w0 row read once, directly from global
    for (int row = tid; row < 1024; row += 512) {
        float a = wd_b0[row], bb = 0.0f;
        const float* wr = wd_w0 + (size_t)row * LATENT;
#pragma unroll
        for (int c = 0; c < LATENT; c++) {
            float w = wr[c];
            a  = fmaf(w, z[c],   a);
            bb = fmaf(w, dzb[c], bb);
        }
        float s = sigf(a);
        g_g1[row] = s;
        g_p1[row] = s * (1.0f - s) * bb;
    }
}

// ---------------------------------------------------------------------------
extern "C" void kernel_launch(void* const* d_in, const int* in_sizes, int n_in,
                              void* d_out, int out_size)
{
    const float* x     = (const float*)d_in[0];
    const float* dx    = (const float*)d_in[1];
    const float* we_w0 = (const float*)d_in[3];
    const float* we_b0 = (const float*)d_in[4];
    const float* we_w1 = (const float*)d_in[5];
    const float* we_b1 = (const float*)d_in[6];
    const float* we_w2 = (const float*)d_in[7];
    const float* we_b2 = (const float*)d_in[8];
    const float* wd_w0 = (const float*)d_in[9];
    const float* wd_b0 = (const float*)d_in[10];
    const float* wd_w1 = (const float*)d_in[11];
    const float* wd_b1 = (const float*)d_in[12];
    const float* wd_w2 = (const float*)d_in[13];
    const float* wd_b2 = (const float*)d_in[14];
    const float* E_w   = (const float*)d_in[15];
    const float* E_b   = (const float*)d_in[16];
    float* out = (float*)d_out;

    cudaLaunchAttribute attr[1];
    attr[0].id = cudaLaunchAttributeProgrammaticStreamSerialization;
    attr[0].val.programmaticStreamSerializationAllowed = 1;

    cudaLaunchConfig_t cfg{};
    cfg.blockDim = dim3(256, 1, 1);
    cfg.dynamicSmemBytes = 0;
    cfg.stream = 0;
    cfg.attrs = attr;
    cfg.numAttrs = 1;

    // 1) enc L0 (256 MB)
    cfg.gridDim = dim3(W0_OUT / 4, 1, 1);
    cudaLaunchKernelEx(&cfg, k_enc0, we_w0, x, dx, we_b0);

    // 2) enc L1 (16 MB, split-K x2) + small-matrix L2 prefetch
    cfg.gridDim = dim3(W1_OUT / 4, 2, 1);
    cudaLaunchKernelEx(&cfg, k_enc1, we_w1, we_b1, we_w2, E_w, wd_w0);

    // 3) middle chain (static smem only now)
    {
        cudaLaunchConfig_t cs = cfg;
        cs.gridDim = dim3(1, 1, 1);
        cs.blockDim = dim3(512, 1, 1);
        cudaLaunchKernelEx(&cs, k_small, we_w2, we_b2, E_w, E_b, wd_w0, wd_b0, out);
    }

    // 4) dec L1 (16 MB)
    cfg.gridDim = dim3(4096 / 4, 1, 1);
    cudaLaunchKernelEx(&cfg, k_dec1, wd_w1, wd_b1);

    // 5) dec L2 (256 MB)
    cfg.gridDim = dim3(16384 / 4, 1, 1);
    cudaLaunchKernelEx(&cfg, k_dec2, wd_w2, wd_b2, out);
}